// round 3
// baseline (speedup 1.0000x reference)
#include <cuda_runtime.h>
#include <cstdint>

#define B_    32
#define H_    128
#define W_    128
#define N_    1024
#define K_    49152          // 3*128*128
#define ROWS_ 384            // K rows of 128
#define SLABS_ 37            // 37*8 = 296 CTAs = 2/SM, one wave
#define NTB_  128            // n columns per CTA

// ---- device scratch (no allocations allowed) ----
__device__ float    g_gy [H_*N_];        // gy[h][n]
__device__ float    g_gxn[W_*N_];        // gx[w][n]*norm[n]
__device__ uint16_t g_xhi[B_*K_];        // x hi bf16
__device__ uint16_t g_xlo[B_*K_];        // x lo bf16
__device__ float    g_part[SLABS_*B_*N_];

// ---- smem layout (bytes) ----
#define SM_GXN 0                          // 128*128*4 = 65536
#define SM_GY  65536                      // up to 11 rows * 512B = 5632
#define SM_A   (65536 + 5632)             // [buf][term] 32*48B = 1536 each, 4 total
#define SM_B   (SM_A + 4*1536)            // [buf][term] 16*272B = 4352 each, 4 total
#define SMEM_TOTAL (SM_B + 4*4352)        // 94720 B

// ---- helpers ----
__device__ __forceinline__ uint32_t pack2(float lo, float hi){
    uint32_t d; asm("cvt.rn.bf16x2.f32 %0, %1, %2;" : "=r"(d) : "f"(hi), "f"(lo)); return d;
}
__device__ __forceinline__ uint32_t s2u(const void* p){
    return (uint32_t)__cvta_generic_to_shared(p);
}
__device__ __forceinline__ void ldsm_x4(uint32_t* r, uint32_t a){
    asm volatile("ldmatrix.sync.aligned.m8n8.x4.shared.b16 {%0,%1,%2,%3}, [%4];"
      : "=r"(r[0]),"=r"(r[1]),"=r"(r[2]),"=r"(r[3]) : "r"(a));
}
__device__ __forceinline__ void ldsm_x4t(uint32_t* r, uint32_t a){
    asm volatile("ldmatrix.sync.aligned.m8n8.x4.trans.shared.b16 {%0,%1,%2,%3}, [%4];"
      : "=r"(r[0]),"=r"(r[1]),"=r"(r[2]),"=r"(r[3]) : "r"(a));
}
__device__ __forceinline__ void mma_bf16(float* c, const uint32_t* a, uint32_t b0, uint32_t b1){
    asm volatile("mma.sync.aligned.m16n8k16.row.col.f32.bf16.bf16.f32 "
      "{%0,%1,%2,%3}, {%4,%5,%6,%7}, {%8,%9}, {%0,%1,%2,%3};"
      : "+f"(c[0]),"+f"(c[1]),"+f"(c[2]),"+f"(c[3])
      : "r"(a[0]),"r"(a[1]),"r"(a[2]),"r"(a[3]),"r"(b0),"r"(b1));
}

// ---- kernel 1: Gaussian tables, block per neuron ----
__global__ void build_tables(const float* __restrict__ mu_x, const float* __restrict__ mu_y,
                             const float* __restrict__ sg_x, const float* __restrict__ sg_y)
{
    __shared__ float red[8];
    int n = blockIdx.x, i = threadIdx.x;           // 128 threads, i = coordinate
    float mx = mu_x[n], my = mu_y[n];
    float isx = 1.f/sg_x[n], isy = 1.f/sg_y[n];
    float g  = (float)i * (1.f/127.f);
    float tx = (g - mx)*isx, ty = (g - my)*isy;
    float vx = expf(-0.5f*tx*tx), vy = expf(-0.5f*ty*ty);
    float sx2 = vx*vx, sy2 = vy*vy;
#pragma unroll
    for (int o = 16; o; o >>= 1){
        sx2 += __shfl_xor_sync(0xffffffffu, sx2, o);
        sy2 += __shfl_xor_sync(0xffffffffu, sy2, o);
    }
    if ((i&31)==0){ red[i>>5] = sx2; red[4+(i>>5)] = sy2; }
    __syncthreads();
    sx2 = red[0]+red[1]+red[2]+red[3];
    sy2 = red[4]+red[5]+red[6]+red[7];
    float nrm = sqrtf((float)(H_*W_)/(sx2*sy2));   // C cancels in normalization
    g_gxn[i*N_ + n] = vx*nrm;
    g_gy [i*N_ + n] = vy;
}

// ---- kernel 2: split x into bf16 hi/lo ----
__global__ void xsplit(const float* __restrict__ x)
{
    int i = blockIdx.x*256 + threadIdx.x;          // over B*K/4 float4s
    float4 v = ((const float4*)x)[i];
    uint32_t h0 = pack2(v.x, v.y);
    uint32_t h1 = pack2(v.z, v.w);
    float r0 = v.x - __uint_as_float(h0<<16);
    float r1 = v.y - __uint_as_float(h0 & 0xffff0000u);
    float r2 = v.z - __uint_as_float(h1<<16);
    float r3 = v.w - __uint_as_float(h1 & 0xffff0000u);
    ((uint2*)g_xhi)[i] = make_uint2(h0, h1);
    ((uint2*)g_xlo)[i] = make_uint2(pack2(r0,r1), pack2(r2,r3));
}

// ---- kernel 3: main masked MMA GEMM ----
__global__ __launch_bounds__(256, 2) void main_kernel(const float* __restrict__ wgt)
{
    extern __shared__ char smem[];
    float* gxn_s = (float*)(smem + SM_GXN);
    float* gy_s  = (float*)(smem + SM_GY);

    const int t     = threadIdx.x;
    const int slab  = blockIdx.x, ntile = blockIdx.y;
    const int nbase = ntile * NTB_;
    const int r0    = slab*ROWS_/SLABS_, r1 = (slab+1)*ROWS_/SLABS_;
    const int rows  = r1 - r0;
    const int nchunks = rows*8;

    // preload gxn slab [128 wcol x 128 n] and gy rows [rows x 128 n]
    for (int i = t; i < (W_*NTB_)/4; i += 256){
        int wc = i>>5, p = (i&31)*4;
        *(float4*)(gxn_s + wc*NTB_ + p) = *(const float4*)(g_gxn + wc*N_ + nbase + p);
    }
    for (int i = t; i < rows*32; i += 256){
        int rr = i>>5, p = (i&31)*4;
        int h = (r0 + rr) & (H_-1);
        *(float4*)(gy_s + rr*NTB_ + p) = *(const float4*)(g_gy + h*N_ + nbase + p);
    }

    const int krow = t>>4, nidx = t&15, n0 = nidx*8;   // B-convert role
    const int xrole = t>>6;                             // 0: stage xhi, 1: stage xlo
    const int xb = (t&63)>>1, xoff = t&1;               // b row, 8-half segment

    const int lane = t & 31, warp = t >> 5;
    const int mat = lane>>3, rowin = lane&7;
    const uint32_t aOff = (uint32_t)(((mat&1)*8 + rowin)*48 + (mat>>1)*16);
    const uint32_t bOff = (uint32_t)(((mat&1)*8 + rowin)*272 + warp*32 + (mat>>1)*16);
    const uint32_t smA = s2u(smem + SM_A), smB = s2u(smem + SM_B);

    // 2-deep register prefetch of weights + x
    float4 wA[2], wB[2];
    uint4  xv[2];

#define LDW(c, s) do { \
    int r_ = r0 + ((c)>>3); \
    size_t kg_ = (size_t)r_*W_ + ((c)&7)*16 + krow; \
    const float4* p_ = (const float4*)(wgt + kg_*N_ + nbase + n0); \
    wA[s] = p_[0]; wB[s] = p_[1]; } while(0)
#define LDX(c, s) do { \
    if (xrole < 2){ \
        int r_ = r0 + ((c)>>3); \
        int kb_ = r_*W_ + ((c)&7)*16; \
        const uint16_t* src_ = (xrole==0) ? g_xhi : g_xlo; \
        xv[s] = *(const uint4*)(src_ + (size_t)xb*K_ + kb_ + xoff*8); } } while(0)

    LDW(0,0); LDX(0,0);
    LDW(1,1); LDX(1,1);

    float acc[2][2][4];
#pragma unroll
    for (int a=0;a<2;a++)
#pragma unroll
        for (int b=0;b<2;b++)
#pragma unroll
            for (int q=0;q<4;q++) acc[a][b][q] = 0.f;

    __syncthreads();   // gxn_s / gy_s ready

    for (int c = 0; c < nchunks; ++c){
        const int buf = c & 1, s = c & 1;

        // ---- convert w -> masked bf16 hi/lo, STS into B tile ----
        {
            const int wcol = (c&7)*16 + krow;
            const int rr   = c>>3;
            float4 ga0 = *(float4*)(gxn_s + wcol*NTB_ + n0);
            float4 ga1 = *(float4*)(gxn_s + wcol*NTB_ + n0 + 4);
            float4 gy0 = *(float4*)(gy_s  + rr*NTB_  + n0);
            float4 gy1 = *(float4*)(gy_s  + rr*NTB_  + n0 + 4);
            float4 w0 = wA[s], w1 = wB[s];
            float wm[8];
            wm[0]=w0.x*ga0.x*gy0.x; wm[1]=w0.y*ga0.y*gy0.y;
            wm[2]=w0.z*ga0.z*gy0.z; wm[3]=w0.w*ga0.w*gy0.w;
            wm[4]=w1.x*ga1.x*gy1.x; wm[5]=w1.y*ga1.y*gy1.y;
            wm[6]=w1.z*ga1.z*gy1.z; wm[7]=w1.w*ga1.w*gy1.w;
            uint32_t h0 = pack2(wm[0],wm[1]), h1 = pack2(wm[2],wm[3]);
            uint32_t h2 = pack2(wm[4],wm[5]), h3 = pack2(wm[6],wm[7]);
            float l0 = wm[0]-__uint_as_float(h0<<16), l1 = wm[1]-__uint_as_float(h0&0xffff0000u);
            float l2 = wm[2]-__uint_as_float(h1<<16), l3 = wm[3]-__uint_as_float(h1&0xffff0000u);
            float l4 = wm[4]-__uint_as_float(h2<<16), l5 = wm[5]-__uint_as_float(h2&0xffff0000u);
            float l6 = wm[6]-__uint_as_float(h3<<16), l7 = wm[7]-__uint_as_float(h3&0xffff0000u);
            *(uint4*)(smem + SM_B + (buf*2+0)*4352 + krow*272 + n0*2)
                = make_uint4(h0,h1,h2,h3);
            *(uint4*)(smem + SM_B + (buf*2+1)*4352 + krow*272 + n0*2)
                = make_uint4(pack2(l0,l1), pack2(l2,l3), pack2(l4,l5), pack2(l6,l7));
            if (xrole < 2)
                *(uint4*)(smem + SM_A + (buf*2+xrole)*1536 + xb*48 + xoff*16) = xv[s];
        }

        // prefetch chunk c+2 (slot s is free after the reads above)
        if (c+2 < nchunks){ LDW(c+2, s); LDX(c+2, s); }

        __syncthreads();

        // ---- fragments + 12 MMAs ----
        uint32_t Ah0[4], Ah1[4], Al0[4], Al1[4], Bh[4], Bl[4];
        uint32_t aH = smA + (buf*2+0)*1536 + aOff;
        uint32_t aL = smA + (buf*2+1)*1536 + aOff;
        ldsm_x4 (Ah0, aH);        ldsm_x4 (Ah1, aH + 768);
        ldsm_x4 (Al0, aL);        ldsm_x4 (Al1, aL + 768);
        ldsm_x4t(Bh,  smB + (buf*2+0)*4352 + bOff);
        ldsm_x4t(Bl,  smB + (buf*2+1)*4352 + bOff);

        mma_bf16(acc[0][0], Ah0, Bh[0], Bh[1]);
        mma_bf16(acc[0][1], Ah0, Bh[2], Bh[3]);
        mma_bf16(acc[1][0], Ah1, Bh[0], Bh[1]);
        mma_bf16(acc[1][1], Ah1, Bh[2], Bh[3]);
        mma_bf16(acc[0][0], Ah0, Bl[0], Bl[1]);
        mma_bf16(acc[0][1], Ah0, Bl[2], Bl[3]);
        mma_bf16(acc[1][0], Ah1, Bl[0], Bl[1]);
        mma_bf16(acc[1][1], Ah1, Bl[2], Bl[3]);
        mma_bf16(acc[0][0], Al0, Bh[0], Bh[1]);
        mma_bf16(acc[0][1], Al0, Bh[2], Bh[3]);
        mma_bf16(acc[1][0], Al1, Bh[0], Bh[1]);
        mma_bf16(acc[1][1], Al1, Bh[2], Bh[3]);
    }
#undef LDW
#undef LDX

    // ---- epilogue: partials ----
    const int grp = lane>>2, tg = lane&3;
    float* pp = g_part + (size_t)slab*(B_*N_);
#pragma unroll
    for (int mt = 0; mt < 2; ++mt)
#pragma unroll
        for (int nb = 0; nb < 2; ++nb){
            int b = mt*16 + grp;
            int n = nbase + warp*16 + nb*8 + tg*2;
            *(float2*)(pp + (size_t)b*N_ + n)     = make_float2(acc[mt][nb][0], acc[mt][nb][1]);
            *(float2*)(pp + (size_t)(b+8)*N_ + n) = make_float2(acc[mt][nb][2], acc[mt][nb][3]);
        }
}

// ---- kernel 4: deterministic split-K reduction ----
__global__ void reduce_k(float* __restrict__ out)
{
    int i = blockIdx.x*256 + threadIdx.x;   // 0 .. B*N-1
    float s = 0.f;
#pragma unroll 1
    for (int j = 0; j < SLABS_; ++j)
        s += g_part[(size_t)j*(B_*N_) + i];
    out[i] = s;
}

extern "C" void kernel_launch(void* const* d_in, const int* in_sizes, int n_in,
                              void* d_out, int out_size)
{
    const float* x   = (const float*)d_in[0];
    const float* mux = (const float*)d_in[1];
    const float* muy = (const float*)d_in[2];
    const float* sx  = (const float*)d_in[3];
    const float* sy  = (const float*)d_in[4];
    const float* wgt = (const float*)d_in[5];

    cudaFuncSetAttribute(main_kernel, cudaFuncAttributeMaxDynamicSharedMemorySize, SMEM_TOTAL);

    build_tables<<<N_, 128>>>(mux, muy, sx, sy);
    xsplit<<<(B_*K_/4)/256, 256>>>(x);
    main_kernel<<<dim3(SLABS_, 8), 256, SMEM_TOTAL>>>(wgt);
    reduce_k<<<(B_*N_)/256, 256>>>((float*)d_out);
}